// round 1
// baseline (speedup 1.0000x reference)
#include <cuda_runtime.h>
#include <math.h>

#define Bb 4
#define Nn 256
#define Cc 32
#define Mm 4
#define OUTD 64

// ---------------- scratch (no allocation allowed) ----------------
__device__ float g_SJ[Bb*Nn*Cc];     // sum_i x[b,i,j,c]   (indexed by j)
__device__ float g_SI[Bb*Nn*Cc];     // sum_j x[b,i,j,c]   (indexed by i)
__device__ float g_DG[Bb*Nn*Cc];     // x[b,n,n,c]
__device__ float g_e [Bb*Nn*Mm];     // sigmoid outputs (neighbs)
__device__ float g_R [Bb*Nn*Mm*Cc];  // sum_i e[i,m] x[b,i,j,c]  (indexed by j)
__device__ float g_Q [Bb*Nn*Mm*Cc];  // sum_j e[j,m] x[b,i,j,c]  (indexed by i)
__device__ float g_C0[Bb*OUTD];
__device__ float g_Add[Bb*Nn*OUTD];

// ---------------- packed f32x2 helpers ----------------
__device__ __forceinline__ unsigned long long pack2(float lo, float hi) {
    unsigned long long r;
    asm("mov.b64 %0, {%1, %2};" : "=l"(r) : "f"(lo), "f"(hi));
    return r;
}
__device__ __forceinline__ unsigned long long fma2(unsigned long long a,
                                                   unsigned long long b,
                                                   unsigned long long c) {
    unsigned long long d;
    asm("fma.rn.f32x2 %0, %1, %2, %3;" : "=l"(d) : "l"(a), "l"(b), "l"(c));
    return d;
}

// ---------------- kernel 1: unweighted contractions ----------------
__global__ void k_contract1(const float* __restrict__ x) {
    int bn = blockIdx.x; int b = bn >> 8; int n = bn & 255;
    int t = threadIdx.x; int c = t & 31; int g = t >> 5;
    const float* xb = x + (size_t)b * Nn * Nn * Cc;
    __shared__ float red[8][32];

    float ca = 0.f;
    #pragma unroll 4
    for (int j = g; j < Nn; j += 8) ca += xb[((size_t)n * Nn + j) * Cc + c];
    red[g][c] = ca; __syncthreads();
    if (g == 0) {
        float s = 0.f;
        #pragma unroll
        for (int q = 0; q < 8; ++q) s += red[q][c];
        g_SI[(b * Nn + n) * Cc + c] = s;
    }
    __syncthreads();

    float ra = 0.f;
    #pragma unroll 4
    for (int i = g; i < Nn; i += 8) ra += xb[((size_t)i * Nn + n) * Cc + c];
    red[g][c] = ra; __syncthreads();
    if (g == 0) {
        float s = 0.f;
        #pragma unroll
        for (int q = 0; q < 8; ++q) s += red[q][c];
        g_SJ[(b * Nn + n) * Cc + c] = s;
    }
    if (t < 32) g_DG[(b * Nn + n) * Cc + t] = xb[((size_t)n * Nn + n) * Cc + t];
}

// ---------------- kernel 2: neighborhood sigmoid ----------------
__global__ void k_neighbs(const float* __restrict__ w1, const float* __restrict__ b1,
                          const float* __restrict__ w0, const float* __restrict__ b0) {
    int b = blockIdx.x; int t = threadIdx.x; int c = t & 31; int g = t >> 5;
    __shared__ float red[8][32];
    __shared__ float s_rcs[32], s_ds[32], sw1[96 * 4], sw0[64 * 4], so0[4];

    for (int k = t; k < 384; k += 256) sw1[k] = w1[k];
    if (t < 256) sw0[t] = w0[t];

    float a = 0.f;
    for (int j = g; j < Nn; j += 8) a += g_SJ[(b * Nn + j) * Cc + c];
    red[g][c] = a; __syncthreads();
    if (g == 0) {
        float s = 0.f;
        #pragma unroll
        for (int q = 0; q < 8; ++q) s += red[q][c];
        s_rcs[c] = s * (1.f / ((float)Nn * (float)Nn));
    }
    __syncthreads();
    a = 0.f;
    for (int j = g; j < Nn; j += 8) a += g_DG[(b * Nn + j) * Cc + c];
    red[g][c] = a; __syncthreads();
    if (g == 0) {
        float s = 0.f;
        #pragma unroll
        for (int q = 0; q < 8; ++q) s += red[q][c];
        s_ds[c] = s * (1.f / (float)Nn);
    }
    __syncthreads();

    if (t < 4) {
        float v = b0[t];
        #pragma unroll 8
        for (int cc = 0; cc < 32; ++cc)
            v += s_rcs[cc] * sw0[cc * 4 + t] + s_ds[cc] * sw0[(32 + cc) * 4 + t];
        so0[t] = v;
    }
    __syncthreads();

    int n = t;
    float nb0 = so0[0] + b1[0], nb1 = so0[1] + b1[1];
    float nb2 = so0[2] + b1[2], nb3 = so0[3] + b1[3];
    const float invN = 1.f / (float)Nn;
    #pragma unroll 4
    for (int cc = 0; cc < 32; ++cc) {
        float rs = g_SJ[(b * Nn + n) * Cc + cc] * invN;
        float cs = g_SI[(b * Nn + n) * Cc + cc] * invN;
        float dg = g_DG[(b * Nn + n) * Cc + cc];
        nb0 += rs * sw1[cc * 4 + 0] + cs * sw1[(32 + cc) * 4 + 0] + dg * sw1[(64 + cc) * 4 + 0];
        nb1 += rs * sw1[cc * 4 + 1] + cs * sw1[(32 + cc) * 4 + 1] + dg * sw1[(64 + cc) * 4 + 1];
        nb2 += rs * sw1[cc * 4 + 2] + cs * sw1[(32 + cc) * 4 + 2] + dg * sw1[(64 + cc) * 4 + 2];
        nb3 += rs * sw1[cc * 4 + 3] + cs * sw1[(32 + cc) * 4 + 3] + dg * sw1[(64 + cc) * 4 + 3];
    }
    g_e[(b * Nn + n) * 4 + 0] = 1.f / (1.f + expf(-nb0));
    g_e[(b * Nn + n) * 4 + 1] = 1.f / (1.f + expf(-nb1));
    g_e[(b * Nn + n) * 4 + 2] = 1.f / (1.f + expf(-nb2));
    g_e[(b * Nn + n) * 4 + 3] = 1.f / (1.f + expf(-nb3));
}

// ---------------- kernel 3: e-weighted contractions ----------------
__global__ void k_weighted(const float* __restrict__ x) {
    int bn = blockIdx.x; int b = bn >> 8; int n = bn & 255;
    int t = threadIdx.x; int c = t & 31; int g = t >> 5;
    __shared__ float se[Nn * 4];
    __shared__ float red[8][4][32];
    for (int k = t; k < Nn * 4; k += 256) se[k] = g_e[b * Nn * 4 + k];
    __syncthreads();
    const float* xb = x + (size_t)b * Nn * Nn * Cc;

    float q0 = 0.f, q1 = 0.f, q2 = 0.f, q3 = 0.f;
    #pragma unroll 4
    for (int j = g; j < Nn; j += 8) {
        float xv = xb[((size_t)n * Nn + j) * Cc + c];
        q0 += se[j * 4 + 0] * xv; q1 += se[j * 4 + 1] * xv;
        q2 += se[j * 4 + 2] * xv; q3 += se[j * 4 + 3] * xv;
    }
    red[g][0][c] = q0; red[g][1][c] = q1; red[g][2][c] = q2; red[g][3][c] = q3;
    __syncthreads();
    if (g < 4) {
        float s = 0.f;
        #pragma unroll
        for (int p = 0; p < 8; ++p) s += red[p][g][c];
        g_Q[((b * Nn + n) * 4 + g) * 32 + c] = s;
    }
    __syncthreads();

    float r0 = 0.f, r1 = 0.f, r2 = 0.f, r3 = 0.f;
    #pragma unroll 4
    for (int i = g; i < Nn; i += 8) {
        float xv = xb[((size_t)i * Nn + n) * Cc + c];
        r0 += se[i * 4 + 0] * xv; r1 += se[i * 4 + 1] * xv;
        r2 += se[i * 4 + 2] * xv; r3 += se[i * 4 + 3] * xv;
    }
    red[g][0][c] = r0; red[g][1][c] = r1; red[g][2][c] = r2; red[g][3][c] = r3;
    __syncthreads();
    if (g < 4) {
        float s = 0.f;
        #pragma unroll
        for (int p = 0; p < 8; ++p) s += red[p][g][c];
        g_R[((b * Nn + n) * 4 + g) * 32 + c] = s;
    }
}

// ---------------- kernel 4a: 0d term (per-b constant) ----------------
__global__ void k_c0(const float* __restrict__ w0d, const float* __restrict__ b0d,
                     const float* __restrict__ b2d) {
    int b = blockIdx.x, t = threadIdx.x;
    __shared__ float obj0[256];
    if (t < 128) {
        int m = t >> 5, c = t & 31;
        float a = 0.f, d = 0.f;
        #pragma unroll 4
        for (int j = 0; j < Nn; ++j) {
            float ev = g_e[(b * Nn + j) * 4 + m];
            a += ev * g_R[((b * Nn + j) * 4 + m) * 32 + c];
            d += ev * ev * g_DG[(b * Nn + j) * Cc + c];
        }
        obj0[t]       = a * (1.f / ((float)Nn * (float)Nn)); // rcs2
        obj0[128 + t] = d * (1.f / (float)Nn);               // ds2
    }
    __syncthreads();
    if (t < 64) {
        float a = b0d[t] + b2d[t];
        #pragma unroll 8
        for (int k = 0; k < 256; ++k) a += obj0[k] * w0d[k * 64 + t];
        g_C0[b * 64 + t] = a;
    }
}

// ---------------- kernel 4b: per-(b,j) additive term ----------------
__global__ void k_add(const float* __restrict__ w1d, const float* __restrict__ b1d) {
    int bn = blockIdx.x; int b = bn >> 8; int n = bn & 255;
    int t = threadIdx.x; // 128 threads
    __shared__ float obj1[384];
    {
        int m = t >> 5, c = t & 31;
        float ev = g_e[(b * Nn + n) * 4 + m];
        const float invN = 1.f / (float)Nn;
        obj1[t]       = ev * g_R[((b * Nn + n) * 4 + m) * 32 + c] * invN;   // rs2
        obj1[128 + t] = ev * g_Q[((b * Nn + n) * 4 + m) * 32 + c] * invN;   // cs2
        obj1[256 + t] = ev * ev * g_DG[(b * Nn + n) * Cc + c];              // dg2
    }
    __syncthreads();
    if (t < 64) {
        float a = b1d[t] + g_C0[b * 64 + t];
        #pragma unroll 8
        for (int k = 0; k < 384; ++k) a += obj1[k] * w1d[k * 64 + t];
        g_Add[(b * Nn + n) * 64 + t] = a;
    }
}

// ---------------- kernel 5: main fused 2d GEMM ----------------
#define SMEM_MAIN_FLOATS (16384 + 8448 + 8448 + 1024 + 64 + 64)

__global__ __launch_bounds__(256, 1)
void k_main(const float* __restrict__ x, const float* __restrict__ w2d,
            float* __restrict__ out) {
    const int b = blockIdx.z;
    const int I = blockIdx.y * 16;
    const int J = blockIdx.x * 16;
    const int t = threadIdx.x;
    const int ti = t >> 4, tj = t & 15;

    extern __shared__ float sm[];
    float* sW   = sm;              // 16384 floats: w2d [256][64]
    float* sXij = sW + 16384;      // 256*33
    float* sXji = sXij + 8448;     // 256*33
    float* sAdd = sXji + 8448;     // 16*64
    float* sEi  = sAdd + 1024;     // 16*4
    float* sEj  = sEi + 64;        // 16*4

    // load w2d (coalesced float4)
    {
        const float4* w4 = (const float4*)w2d;
        float4* sW4 = (float4*)sW;
        #pragma unroll
        for (int k = 0; k < 16; ++k) sW4[k * 256 + t] = w4[k * 256 + t];
    }
    // load x tiles (padded stride 33 -> conflict free reads)
    const float* xb = x + (size_t)b * Nn * Nn * Cc;
    #pragma unroll 2
    for (int r = 0; r < 16; ++r) {
        const float* srcij = xb + (((size_t)(I + r)) * Nn + J) * Cc;
        const float* srcji = xb + (((size_t)(J + r)) * Nn + I) * Cc;
        int i1 = t, i2 = t + 256;
        sXij[(r * 16 + (i1 >> 5)) * 33 + (i1 & 31)] = srcij[i1];
        sXij[(r * 16 + (i2 >> 5)) * 33 + (i2 & 31)] = srcij[i2];
        sXji[(r * 16 + (i1 >> 5)) * 33 + (i1 & 31)] = srcji[i1];
        sXji[(r * 16 + (i2 >> 5)) * 33 + (i2 & 31)] = srcji[i2];
    }
    for (int k = t; k < 1024; k += 256) sAdd[k] = g_Add[(b * Nn + J) * 64 + k];
    if (t < 64) sEi[t] = g_e[(b * Nn + I) * 4 + t];
    else if (t < 128) sEj[t - 64] = g_e[(b * Nn + J) * 4 + (t - 64)];
    __syncthreads();

    float sarr[4];
    #pragma unroll
    for (int m = 0; m < 4; ++m) sarr[m] = sEi[ti * 4 + m] * sEj[tj * 4 + m];

    const float* xi = &sXij[(ti * 16 + tj) * 33];
    const float* xj = &sXji[(tj * 16 + ti) * 33];
    float* op = out + ((((size_t)b * Nn + I + ti)) * Nn + J + tj) * 64;

    #pragma unroll 1
    for (int oc = 0; oc < 4; ++oc) {
        unsigned long long acc[8];
        {
            const unsigned long long* ap = (const unsigned long long*)&sAdd[tj * 64 + oc * 16];
            #pragma unroll
            for (int k = 0; k < 8; ++k) acc[k] = ap[k];
        }
        #pragma unroll 1
        for (int m = 0; m < 4; ++m) {
            float sv = sarr[m];
            const float* wabase = &sW[(m * 32) * 64 + oc * 16];
            const float* wbbase = &sW[(128 + m * 32) * 64 + oc * 16];
            #pragma unroll 4
            for (int c = 0; c < 32; ++c) {
                float av = sv * xi[c];
                float bv = sv * xj[c];
                unsigned long long ap2 = pack2(av, av);
                unsigned long long bp2 = pack2(bv, bv);
                const ulonglong2* wa = (const ulonglong2*)(wabase + c * 64);
                const ulonglong2* wb = (const ulonglong2*)(wbbase + c * 64);
                #pragma unroll
                for (int qq = 0; qq < 4; ++qq) {
                    ulonglong2 wav = wa[qq];
                    acc[2 * qq + 0] = fma2(ap2, wav.x, acc[2 * qq + 0]);
                    acc[2 * qq + 1] = fma2(ap2, wav.y, acc[2 * qq + 1]);
                }
                #pragma unroll
                for (int qq = 0; qq < 4; ++qq) {
                    ulonglong2 wbv = wb[qq];
                    acc[2 * qq + 0] = fma2(bp2, wbv.x, acc[2 * qq + 0]);
                    acc[2 * qq + 1] = fma2(bp2, wbv.y, acc[2 * qq + 1]);
                }
            }
        }
        ulonglong2* o2 = (ulonglong2*)(op + oc * 16);
        #pragma unroll
        for (int k = 0; k < 4; ++k) {
            ulonglong2 v; v.x = acc[2 * k]; v.y = acc[2 * k + 1];
            o2[k] = v;
        }
    }
}

// ---------------- launcher ----------------
extern "C" void kernel_launch(void* const* d_in, const int* in_sizes, int n_in,
                              void* d_out, int out_size) {
    const float* x     = (const float*)d_in[0];
    const float* w1_nb = (const float*)d_in[1];
    const float* b1_nb = (const float*)d_in[2];
    const float* w0_nb = (const float*)d_in[3];
    const float* b0_nb = (const float*)d_in[4];
    const float* w2d   = (const float*)d_in[5];
    const float* b2d   = (const float*)d_in[6];
    const float* w1d   = (const float*)d_in[7];
    const float* b1d   = (const float*)d_in[8];
    const float* w0d   = (const float*)d_in[9];
    const float* b0d   = (const float*)d_in[10];
    float* out = (float*)d_out;

    k_contract1<<<Bb * Nn, 256>>>(x);
    k_neighbs<<<Bb, 256>>>(w1_nb, b1_nb, w0_nb, b0_nb);
    k_weighted<<<Bb * Nn, 256>>>(x);
    k_c0<<<Bb, 256>>>(w0d, b0d, b2d);
    k_add<<<Bb * Nn, 128>>>(w1d, b1d);

    cudaFuncSetAttribute(k_main, cudaFuncAttributeMaxDynamicSharedMemorySize,
                         SMEM_MAIN_FLOATS * (int)sizeof(float));
    dim3 grid(Nn / 16, Nn / 16, Bb);
    k_main<<<grid, 256, SMEM_MAIN_FLOATS * (int)sizeof(float)>>>(x, w2d, out);
}

// round 10
// speedup vs baseline: 2.8552x; 2.8552x over previous
#include <cuda_runtime.h>
#include <cuda_bf16.h>
#include <math.h>
#include <cstdint>

#define Bb 4
#define Nn 256
#define Cc 32
#define Mm 4
#define OUTD 64

// ---------------- scratch (no allocation allowed) ----------------
__device__ float g_SJ[Bb*Nn*Cc];
__device__ float g_SI[Bb*Nn*Cc];
__device__ float g_DG[Bb*Nn*Cc];
__device__ float g_e [Bb*Nn*Mm];
__device__ float g_R [Bb*Nn*Mm*Cc];
__device__ float g_Q [Bb*Nn*Mm*Cc];
__device__ float g_C0[Bb*OUTD];
__device__ float g_Add[Bb*Nn*OUTD];
// bf16 weights, [n=256 rows][k=128]: [WA_hi(c 0-31) | WB_hi | WA_lo | WB_lo]
__device__ uint4 g_Wb4[256 * 128 * 2 / 16];

// ---------------- kernel 1: unweighted contractions ----------------
__global__ void k_contract1(const float* __restrict__ x) {
    int bn = blockIdx.x; int b = bn >> 8; int n = bn & 255;
    int t = threadIdx.x; int c = t & 31; int g = t >> 5;
    const float* xb = x + (size_t)b * Nn * Nn * Cc;
    __shared__ float red[8][32];

    float ca = 0.f;
    #pragma unroll 4
    for (int j = g; j < Nn; j += 8) ca += xb[((size_t)n * Nn + j) * Cc + c];
    red[g][c] = ca; __syncthreads();
    if (g == 0) {
        float s = 0.f;
        #pragma unroll
        for (int q = 0; q < 8; ++q) s += red[q][c];
        g_SI[(b * Nn + n) * Cc + c] = s;
    }
    __syncthreads();

    float ra = 0.f;
    #pragma unroll 4
    for (int i = g; i < Nn; i += 8) ra += xb[((size_t)i * Nn + n) * Cc + c];
    red[g][c] = ra; __syncthreads();
    if (g == 0) {
        float s = 0.f;
        #pragma unroll
        for (int q = 0; q < 8; ++q) s += red[q][c];
        g_SJ[(b * Nn + n) * Cc + c] = s;
    }
    if (t < 32) g_DG[(b * Nn + n) * Cc + t] = xb[((size_t)n * Nn + n) * Cc + t];
}

// ---------------- kernel 2: neighborhood sigmoid ----------------
__global__ void k_neighbs(const float* __restrict__ w1, const float* __restrict__ b1,
                          const float* __restrict__ w0, const float* __restrict__ b0) {
    int b = blockIdx.x; int t = threadIdx.x; int c = t & 31; int g = t >> 5;
    __shared__ float red[8][32];
    __shared__ float s_rcs[32], s_ds[32], sw1[96 * 4], sw0[64 * 4], so0[4];

    for (int k = t; k < 384; k += 256) sw1[k] = w1[k];
    if (t < 256) sw0[t] = w0[t];

    float a = 0.f;
    for (int j = g; j < Nn; j += 8) a += g_SJ[(b * Nn + j) * Cc + c];
    red[g][c] = a; __syncthreads();
    if (g == 0) {
        float s = 0.f;
        #pragma unroll
        for (int q = 0; q < 8; ++q) s += red[q][c];
        s_rcs[c] = s * (1.f / ((float)Nn * (float)Nn));
    }
    __syncthreads();
    a = 0.f;
    for (int j = g; j < Nn; j += 8) a += g_DG[(b * Nn + j) * Cc + c];
    red[g][c] = a; __syncthreads();
    if (g == 0) {
        float s = 0.f;
        #pragma unroll
        for (int q = 0; q < 8; ++q) s += red[q][c];
        s_ds[c] = s * (1.f / (float)Nn);
    }
    __syncthreads();

    if (t < 4) {
        float v = b0[t];
        #pragma unroll 8
        for (int cc = 0; cc < 32; ++cc)
            v += s_rcs[cc] * sw0[cc * 4 + t] + s_ds[cc] * sw0[(32 + cc) * 4 + t];
        so0[t] = v;
    }
    __syncthreads();

    int n = t;
    float nb0 = so0[0] + b1[0], nb1 = so0[1] + b1[1];
    float nb2 = so0[2] + b1[2], nb3 = so0[3] + b1[3];
    const float invN = 1.f / (float)Nn;
    #pragma unroll 4
    for (int cc = 0; cc < 32; ++cc) {
        float rs = g_SJ[(b * Nn + n) * Cc + cc] * invN;
        float cs = g_SI[(b * Nn + n) * Cc + cc] * invN;
        float dg = g_DG[(b * Nn + n) * Cc + cc];
        nb0 += rs * sw1[cc * 4 + 0] + cs * sw1[(32 + cc) * 4 + 0] + dg * sw1[(64 + cc) * 4 + 0];
        nb1 += rs * sw1[cc * 4 + 1] + cs * sw1[(32 + cc) * 4 + 1] + dg * sw1[(64 + cc) * 4 + 1];
        nb2 += rs * sw1[cc * 4 + 2] + cs * sw1[(32 + cc) * 4 + 2] + dg * sw1[(64 + cc) * 4 + 2];
        nb3 += rs * sw1[cc * 4 + 3] + cs * sw1[(32 + cc) * 4 + 3] + dg * sw1[(64 + cc) * 4 + 3];
    }
    g_e[(b * Nn + n) * 4 + 0] = 1.f / (1.f + expf(-nb0));
    g_e[(b * Nn + n) * 4 + 1] = 1.f / (1.f + expf(-nb1));
    g_e[(b * Nn + n) * 4 + 2] = 1.f / (1.f + expf(-nb2));
    g_e[(b * Nn + n) * 4 + 3] = 1.f / (1.f + expf(-nb3));
}

// ---------------- kernel 3: e-weighted contractions ----------------
__global__ void k_weighted(const float* __restrict__ x) {
    int bn = blockIdx.x; int b = bn >> 8; int n = bn & 255;
    int t = threadIdx.x; int c = t & 31; int g = t >> 5;
    __shared__ float se[Nn * 4];
    __shared__ float red[8][4][32];
    for (int k = t; k < Nn * 4; k += 256) se[k] = g_e[b * Nn * 4 + k];
    __syncthreads();
    const float* xb = x + (size_t)b * Nn * Nn * Cc;

    float q0 = 0.f, q1 = 0.f, q2 = 0.f, q3 = 0.f;
    #pragma unroll 4
    for (int j = g; j < Nn; j += 8) {
        float xv = xb[((size_t)n * Nn + j) * Cc + c];
        q0 += se[j * 4 + 0] * xv; q1 += se[j * 4 + 1] * xv;
        q2 += se[j * 4 + 2] * xv; q3 += se[j * 4 + 3] * xv;
    }
    red[g][0][c] = q0; red[g][1][c] = q1; red[g][2][c] = q2; red[g][3][c] = q3;
    __syncthreads();
    if (g < 4) {
        float s = 0.f;
        #pragma unroll
        for (int p = 0; p < 8; ++p) s += red[p][g][c];
        g_Q[((b * Nn + n) * 4 + g) * 32 + c] = s;
    }
    __syncthreads();

    float r0 = 0.f, r1 = 0.f, r2 = 0.f, r3 = 0.f;
    #pragma unroll 4
    for (int i = g; i < Nn; i += 8) {
        float xv = xb[((size_t)i * Nn + n) * Cc + c];
        r0 += se[i * 4 + 0] * xv; r1 += se[i * 4 + 1] * xv;
        r2 += se[i * 4 + 2] * xv; r3 += se[i * 4 + 3] * xv;
    }
    red[g][0][c] = r0; red[g][1][c] = r1; red[g][2][c] = r2; red[g][3][c] = r3;
    __syncthreads();
    if (g < 4) {
        float s = 0.f;
        #pragma unroll
        for (int p = 0; p < 8; ++p) s += red[p][g][c];
        g_R[((b * Nn + n) * 4 + g) * 32 + c] = s;
    }
}

// ---------------- kernel 4a: 0d term, parallelized ----------------
__global__ void k_c0(const float* __restrict__ w0d, const float* __restrict__ b0d,
                     const float* __restrict__ b2d) {
    int b = blockIdx.x, t = threadIdx.x; // 1024 threads
    __shared__ float redA[8][128], redD[8][128];
    __shared__ float obj0[256];
    __shared__ float redM[8][64];
    {
        int g = t >> 7, mc = t & 127, m = mc >> 5, c = mc & 31;
        float a = 0.f, d = 0.f;
        #pragma unroll 4
        for (int j = g; j < Nn; j += 8) {
            float ev = g_e[(b * Nn + j) * 4 + m];
            a += ev * g_R[((b * Nn + j) * 4 + m) * 32 + c];
            d += ev * ev * g_DG[(b * Nn + j) * Cc + c];
        }
        redA[g][mc] = a; redD[g][mc] = d;
    }
    __syncthreads();
    if (t < 128) {
        float sa = 0.f, sd = 0.f;
        #pragma unroll
        for (int q = 0; q < 8; ++q) { sa += redA[q][t]; sd += redD[q][t]; }
        obj0[t]       = sa * (1.f / ((float)Nn * (float)Nn));
        obj0[128 + t] = sd * (1.f / (float)Nn);
    }
    __syncthreads();
    if (t < 512) {
        int o = t & 63, q = t >> 6;
        float s = 0.f;
        #pragma unroll 4
        for (int k = q; k < 256; k += 8) s += obj0[k] * w0d[k * 64 + o];
        redM[q][o] = s;
    }
    __syncthreads();
    if (t < 64) {
        float s = b0d[t] + b2d[t];
        #pragma unroll
        for (int q = 0; q < 8; ++q) s += redM[q][t];
        g_C0[b * 64 + t] = s;
    }
}

// ---------------- kernel 4b: per-(b,j) additive term ----------------
__global__ void k_add(const float* __restrict__ w1d, const float* __restrict__ b1d) {
    int bn = blockIdx.x; int b = bn >> 8; int n = bn & 255;
    int t = threadIdx.x; // 128 threads
    __shared__ float obj1[384];
    {
        int m = t >> 5, c = t & 31;
        float ev = g_e[(b * Nn + n) * 4 + m];
        const float invN = 1.f / (float)Nn;
        obj1[t]       = ev * g_R[((b * Nn + n) * 4 + m) * 32 + c] * invN;
        obj1[128 + t] = ev * g_Q[((b * Nn + n) * 4 + m) * 32 + c] * invN;
        obj1[256 + t] = ev * ev * g_DG[(b * Nn + n) * Cc + c];
    }
    __syncthreads();
    if (t < 64) {
        float a = b1d[t] + g_C0[b * 64 + t];
        #pragma unroll 8
        for (int k = 0; k < 384; ++k) a += obj1[k] * w1d[k * 64 + t];
        g_Add[(b * Nn + n) * 64 + t] = a;
    }
}

// ---------------- kernel W-prep: split w2d into bf16 hi/lo ----------------
// g_Wb layout (bf16): [n=256 rows][k=128] = [WA_hi | WB_hi | WA_lo | WB_lo]
// WA[n=m*64+o][c] = w2d[(m*32+c)*64 + o], WB uses +128 row offset in w2d.
__global__ void k_wprep(const float* __restrict__ w2d) {
    int idx = blockIdx.x * 256 + threadIdx.x; // 8192 = 256 n * 32 c
    if (idx >= 8192) return;
    int n = idx >> 5, c = idx & 31;
    int m = n >> 6, o = n & 63;
    float vA = w2d[(m * 32 + c) * 64 + o];
    float vB = w2d[(128 + m * 32 + c) * 64 + o];
    __nv_bfloat16 hA = __float2bfloat16_rn(vA);
    __nv_bfloat16 lA = __float2bfloat16_rn(vA - __bfloat162float(hA));
    __nv_bfloat16 hB = __float2bfloat16_rn(vB);
    __nv_bfloat16 lB = __float2bfloat16_rn(vB - __bfloat162float(hB));
    __nv_bfloat16* W = (__nv_bfloat16*)g_Wb4;
    W[n * 128 + c]      = hA;
    W[n * 128 + 32 + c] = hB;
    W[n * 128 + 64 + c] = lA;
    W[n * 128 + 96 + c] = lB;
}

// ---------------- main mma.sync kernel ----------------
// Block = (b, i, jhalf): 128 points (i, J..J+127) x 256 N outputs.
// 512 threads = 16 warps: warp w -> mrow = w&7 (16 points), ngrp = w>>3 (128 N).
// A smem [128 r][136 k] bf16: [XijH | XjiH | XijL | XjiL] (c blocks of 32)
// B smem [256 n][136 k] bf16: [WAH | WBH | WAL | WBL]
// 12 ksteps of m16n8k16: (HH x4) (LH x4) (HL x4).
#define RSA 136
#define RSB 136
#define RSR 68
#define OFF_A 0
#define OFF_B 34816
#define OFF_R0 104448
#define OFF_R1 139264
#define OFF_SEJ 174080
#define SM_BYTES 176128

__device__ __forceinline__ void mma_bf16(float* c, uint32_t a0, uint32_t a1,
                                         uint32_t a2, uint32_t a3,
                                         uint32_t b0, uint32_t b1) {
    asm volatile(
        "mma.sync.aligned.m16n8k16.row.col.f32.bf16.bf16.f32 "
        "{%0,%1,%2,%3}, {%4,%5,%6,%7}, {%8,%9}, {%0,%1,%2,%3};"
        : "+f"(c[0]), "+f"(c[1]), "+f"(c[2]), "+f"(c[3])
        : "r"(a0), "r"(a1), "r"(a2), "r"(a3), "r"(b0), "r"(b1));
}

__global__ __launch_bounds__(512, 1)
void k_main_mma(const float* __restrict__ x, float* __restrict__ out) {
    const int b = blockIdx.z;
    const int i = blockIdx.y;
    const int J = blockIdx.x * 128;
    const int tid = threadIdx.x;
    const int w = tid >> 5, lane = tid & 31;
    const int g = lane >> 2, tig = lane & 3;
    const int mrow = w & 7, ngrp = w >> 3;

    extern __shared__ char sm[];
    __nv_bfloat16* Asm = (__nv_bfloat16*)(sm + OFF_A);
    __nv_bfloat16* Bsm = (__nv_bfloat16*)(sm + OFF_B);
    float* R0  = (float*)(sm + OFF_R0);
    float* R1  = (float*)(sm + OFF_R1);
    float* sej = (float*)(sm + OFF_SEJ);

    // ---- stage B: global bf16 -> smem with row padding 128->136 ----
    {
        const uint4* src = g_Wb4;
        #pragma unroll
        for (int it = 0; it < 8; ++it) {
            int lin = it * 512 + tid;            // 4096 uint4
            int row = lin >> 4, seg = lin & 15;
            *(uint4*)&Bsm[row * RSB + seg * 8] = src[lin];
        }
    }

    // ---- stage A: Xij contiguous (float4), split to bf16 hi/lo ----
    {
        const float4* xij4 = (const float4*)(x + (((size_t)b * Nn + i) * Nn + J) * Cc);
        #pragma unroll
        for (int it = 0; it < 2; ++it) {
            int q = it * 512 + tid;              // 1024 float4
            int r = q >> 3, c0 = (q & 7) * 4;
            float4 v = xij4[q];
            float vv[4] = {v.x, v.y, v.z, v.w};
            #pragma unroll
            for (int p = 0; p < 2; ++p) {
                __nv_bfloat16 h0 = __float2bfloat16_rn(vv[2*p]);
                __nv_bfloat16 h1 = __float2bfloat16_rn(vv[2*p+1]);
                __nv_bfloat16 l0 = __float2bfloat16_rn(vv[2*p] - __bfloat162float(h0));
                __nv_bfloat16 l1 = __float2bfloat16_rn(vv[2*p+1] - __bfloat162float(h1));
                *(__nv_bfloat162*)&Asm[r * RSA + c0 + 2*p]      = __halves2bfloat162(h0, h1);
                *(__nv_bfloat162*)&Asm[r * RSA + 64 + c0 + 2*p] = __halves2bfloat162(l0, l1);
            }
        }
    }
    // ---- stage A: Xji rows (warp per row) ----
    {
        #pragma unroll
        for (int rr = w; rr < 128; rr += 16) {
            float v = x[(((size_t)b * Nn + (J + rr)) * Nn + i) * Cc + lane];
            __nv_bfloat16 h = __float2bfloat16_rn(v);
            __nv_bfloat16 l = __float2bfloat16_rn(v - __bfloat162float(h));
            Asm[rr * RSA + 32 + lane] = h;
            Asm[rr * RSA + 96 + lane] = l;
        }
    }
    // ---- stage sej: s[r][m] = e_i[m] * e_{J+r}[m] ----
    {
        int r = tid >> 2, m = tid & 3;
        sej[tid] = g_e[((size_t)b * Nn + i) * 4 + m] * g_e[((size_t)b * Nn + J + r) * 4 + m];
    }
    __syncthreads();

    // ---- MMA mainloop: 12 ksteps, 16 n-tiles each ----
    float acc[16][4];
    #pragma unroll
    for (int u = 0; u < 16; ++u) {
        acc[u][0] = 0.f; acc[u][1] = 0.f; acc[u][2] = 0.f; acc[u][3] = 0.f;
    }

    const int arow0 = mrow * 16 + g;
    const int aoffs[12] = {0,16,32,48, 64,80,96,112, 0,16,32,48};
    const int boffs[12] = {0,16,32,48, 0,16,32,48, 64,80,96,112};

    #pragma unroll
    for (int s = 0; s < 12; ++s) {
        int ak = aoffs[s] + 2 * tig;
        int bk = boffs[s] + 2 * tig;
        uint32_t a0 = *(const uint32_t*)&Asm[arow0 * RSA + ak];
        uint32_t a1 = *(const uint32_t*)&Asm[(arow0 + 8) * RSA + ak];
        uint32_t a2 = *(const uint32_t*)&Asm[arow0 * RSA + ak + 8];
        uint32_t a3 = *(const uint32_t*)&Asm[(arow0 + 8) * RSA + ak + 8];
        #pragma unroll
        for (int u = 0; u < 16; ++u) {
            int nrow = ngrp * 128 + u * 8 + g;
            uint32_t b0 = *(const uint32_t*)&Bsm[nrow * RSB + bk];
            uint32_t b1 = *(const uint32_t*)&Bsm[nrow * RSB + bk + 8];
            mma_bf16(acc[u], a0, a1, a2, a3, b0, b1);
        }
    }

    // ---- epilogue: contract over m into R[point][o] (per n-group buffer) ----
    {
        float* Rb = (ngrp == 0) ? R0 : R1;
        int m0 = ngrp * 2, m1 = m0 + 1;
        int r0 = arow0, r1 = arow0 + 8;
        float s00 = sej[r0 * 4 + m0], s01 = sej[r0 * 4 + m1];
        float s10 = sej[r1 * 4 + m0], s11 = sej[r1 * 4 + m1];
        #pragma unroll
        for (int oct = 0; oct < 8; ++oct) {
            int o = oct * 8 + tig * 2;
            float2 v0, v1;
            v0.x = s00 * acc[oct][0] + s01 * acc[oct + 8][0];
            v0.y = s00 * acc[oct][1] + s01 * acc[oct + 8][1];
            v1.x = s10 * acc[oct][2] + s11 * acc[oct + 8][2];
            v1.y = s10 * acc[oct][3] + s11 * acc[oct + 8][3];
            *(float2*)&Rb[r0 * RSR + o] = v0;
            *(float2*)&Rb[r1 * RSR + o] = v1;
        }
    }
    __syncthreads();

    // ---- final merge: out = R0 + R1 + Add ----
    {
        const float4* add4 = (const float4*)(g_Add + ((size_t)b * Nn + J) * 64);
        float4* out4 = (float4*)(out + (((size_t)b * Nn + i) * Nn + J) * 64);
        #pragma unroll
        for (int it = 0; it < 4; ++it) {
            int lin = it * 512 + tid;           // 2048 float4
            int r = lin >> 4, o4 = (lin & 15) * 4;
            float4 a = add4[r * 16 + (lin & 15)];
            float4 p = *(const float4*)&R0[r * RSR + o4];
            float4 q = *(const float4*)&R1[r * RSR + o4];
            float4 v;
            v.x = a.x + p.x + q.x; v.y = a.y + p.y + q.y;
            v.z = a.z + p.z + q.z; v.w = a.w + p.w + q.w;
            out4[lin] = v;
        }
    }
}

// ---------------- launcher ----------------
extern "C" void kernel_launch(void* const* d_in, const int* in_sizes, int n_in,
                              void* d_out, int out_size) {
    const float* x     = (const float*)d_in[0];
    const float* w1_nb = (const float*)d_in[1];
    const float* b1_nb = (const float*)d_in[2];
    const float* w0_nb = (const float*)d_in[3];
    const float* b0_nb = (const float*)d_in[4];
    const float* w2d   = (const float*)d_in[5];
    const float* b2d   = (const float*)d_in[6];
    const float* w1d   = (const float*)d_in[7];
    const float* b1d   = (const float*)d_in[8];
    const float* w0d   = (const float*)d_in[9];
    const float* b0d   = (const float*)d_in[10];
    float* out = (float*)d_out;

    k_wprep<<<32, 256>>>(w2d);
    k_contract1<<<Bb * Nn, 256>>>(x);
    k_neighbs<<<Bb, 256>>>(w1_nb, b1_nb, w0_nb, b0_nb);
    k_weighted<<<Bb * Nn, 256>>>(x);
    k_c0<<<Bb, 1024>>>(w0d, b0d, b2d);
    k_add<<<Bb * Nn, 128>>>(w1d, b1d);

    cudaFuncSetAttribute(k_main_mma, cudaFuncAttributeMaxDynamicSharedMemorySize, SM_BYTES);
    dim3 grid(Nn / 128, Nn, Bb);
    k_main_mma<<<grid, 512, SM_BYTES>>>(x, out);
}